// round 17
// baseline (speedup 1.0000x reference)
#include <cuda_runtime.h>
#include <cuda_bf16.h>
#include <math.h>
#include <stdint.h>

// Problem constants
#define BATCH   4
#define SEQ     2048
#define DMODEL  1024
#define NHEAD   16
#define HD      64
#define ROWS    (BATCH*SEQ)      // 8192
#define TD      (3*DMODEL)       // 3072
#define NBH     (BATCH*NHEAD)    // 64

// Scratch (__device__ globals; addresses NEVER passed from host — ATS makes
// host-shadow writes silently succeed on GB300, see R14/R15 post-mortem)
__device__ __nv_bfloat16 g_xhi[(size_t)ROWS*DMODEL],  g_xlo[(size_t)ROWS*DMODEL];
__device__ __nv_bfloat16 g_w1hi[(size_t)TD*DMODEL],   g_w1lo[(size_t)TD*DMODEL];
__device__ __nv_bfloat16 g_w2hi[(size_t)DMODEL*DMODEL], g_w2lo[(size_t)DMODEL*DMODEL];
// Per-head q/k/v (written by gemm1 epilogue; Q pre-scaled by 1/8), [bh][s][64]
__device__ __nv_bfloat16 g_qhi[(size_t)NBH*SEQ*HD], g_qlo[(size_t)NBH*SEQ*HD];
__device__ __nv_bfloat16 g_khi[(size_t)NBH*SEQ*HD], g_klo[(size_t)NBH*SEQ*HD];
__device__ __nv_bfloat16 g_vhi[(size_t)NBH*SEQ*HD], g_vlo[(size_t)NBH*SEQ*HD];
// Attention output, bf16 hi/lo, [B*N, D]
__device__ __nv_bfloat16 g_ahi[(size_t)ROWS*DMODEL], g_alo[(size_t)ROWS*DMODEL];

// ===========================================================================
// helpers (base ISA; fragment mappings verified R10/R12/R16)
// ===========================================================================
__device__ __forceinline__ uint32_t smem_u32(const void* p) {
    uint32_t a;
    asm("{ .reg .u64 t; cvta.to.shared.u64 t, %1; cvt.u32.u64 %0, t; }"
        : "=r"(a) : "l"(p));
    return a;
}

__device__ __forceinline__ void ldmatrix_x4(uint32_t& r0, uint32_t& r1,
                                            uint32_t& r2, uint32_t& r3,
                                            uint32_t addr) {
    asm volatile("ldmatrix.sync.aligned.m8n8.x4.shared.b16 {%0,%1,%2,%3}, [%4];"
                 : "=r"(r0), "=r"(r1), "=r"(r2), "=r"(r3) : "r"(addr));
}

__device__ __forceinline__ void ldmatrix_x2(uint32_t& r0, uint32_t& r1,
                                            uint32_t addr) {
    asm volatile("ldmatrix.sync.aligned.m8n8.x2.shared.b16 {%0,%1}, [%2];"
                 : "=r"(r0), "=r"(r1) : "r"(addr));
}

__device__ __forceinline__ void ldmatrix_x2t(uint32_t& r0, uint32_t& r1,
                                             uint32_t addr) {
    asm volatile("ldmatrix.sync.aligned.m8n8.x2.trans.shared.b16 {%0,%1}, [%2];"
                 : "=r"(r0), "=r"(r1) : "r"(addr));
}

__device__ __forceinline__ void mma_bf16(float* d, const uint32_t* a,
                                         const uint32_t* b) {
    asm volatile(
        "mma.sync.aligned.m16n8k16.row.col.f32.bf16.bf16.f32 "
        "{%0,%1,%2,%3}, {%4,%5,%6,%7}, {%8,%9}, {%0,%1,%2,%3};"
        : "+f"(d[0]), "+f"(d[1]), "+f"(d[2]), "+f"(d[3])
        : "r"(a[0]), "r"(a[1]), "r"(a[2]), "r"(a[3]), "r"(b[0]), "r"(b[1]));
}

// pack two fp32 -> bf16x2 (first arg lands in the LOW half)
__device__ __forceinline__ uint32_t pack_bf16(float lo, float hi) {
    uint32_t r;
    asm("cvt.rn.bf16x2.f32 %0, %1, %2;" : "=r"(r) : "f"(hi), "f"(lo));
    return r;
}

// cp.async 16B + group ops
__device__ __forceinline__ void cp16(uint32_t saddr, const void* g) {
    asm volatile("cp.async.cg.shared.global [%0], [%1], 16;"
                 :: "r"(saddr), "l"(g));
}
__device__ __forceinline__ void cp_commit() {
    asm volatile("cp.async.commit_group;");
}
#define CP_WAIT(N) asm volatile("cp.async.wait_group %0;" :: "n"(N))

// GEMM smem tile: rows x 32 bf16 (64 B/row), 16B chunks XOR-swizzled
__device__ __forceinline__ uint32_t tile_off(int r, int c) {
    return (uint32_t)(r * 64 + (((c ^ ((r >> 1) & 3)) & 3) << 4));
}

// Attention smem tile: rows of 64 bf16 (128 B/row), 8 chunks, SW128-style
__device__ __forceinline__ uint32_t swz128(int r, int c) {
    return (uint32_t)(r * 128 + (((c ^ (r & 7)) & 7) << 4));
}

// split 8 fp32 -> bf16 hi + lo (one uint4 each)
__device__ __forceinline__ void split8v(const float* v, uint4& hi, uint4& lo) {
    uint32_t h[4], l[4];
    #pragma unroll
    for (int p = 0; p < 4; p++) {
        float a = v[2*p], b = v[2*p+1];
        __nv_bfloat16 ha = __float2bfloat16_rn(a);
        __nv_bfloat16 hb = __float2bfloat16_rn(b);
        float ra = a - __bfloat162float(ha);
        float rb = b - __bfloat162float(hb);
        __nv_bfloat162 hh = __halves2bfloat162(ha, hb);
        __nv_bfloat162 ll = __halves2bfloat162(__float2bfloat16_rn(ra),
                                               __float2bfloat16_rn(rb));
        h[p] = *reinterpret_cast<uint32_t*>(&hh);
        l[p] = *reinterpret_cast<uint32_t*>(&ll);
    }
    hi = make_uint4(h[0], h[1], h[2], h[3]);
    lo = make_uint4(l[0], l[1], l[2], l[3]);
}

// split one fp32 pair -> hi uint32 + lo uint32
__device__ __forceinline__ void split2(float a, float b, uint32_t& hi, uint32_t& lo) {
    __nv_bfloat16 ha = __float2bfloat16_rn(a);
    __nv_bfloat16 hb = __float2bfloat16_rn(b);
    __nv_bfloat162 hh = __halves2bfloat162(ha, hb);
    hi = *reinterpret_cast<uint32_t*>(&hh);
    float ra = a - __bfloat162float(ha);
    float rb = b - __bfloat162float(hb);
    __nv_bfloat162 ll = __halves2bfloat162(__float2bfloat16_rn(ra),
                                           __float2bfloat16_rn(rb));
    lo = *reinterpret_cast<uint32_t*>(&ll);
}

// ---------------------------------------------------------------------------
// presplit: fp32 array -> bf16 hi/lo GLOBALS (bound in device code)
// ---------------------------------------------------------------------------
__device__ __forceinline__ void presplit_body(const float* __restrict__ s,
                                              __nv_bfloat16* __restrict__ hi,
                                              __nv_bfloat16* __restrict__ lo)
{
    const size_t i = ((size_t)blockIdx.x * 256 + threadIdx.x) * 8;
    float v[8];
    *(float4*)&v[0] = *(const float4*)&s[i];
    *(float4*)&v[4] = *(const float4*)&s[i + 4];
    uint4 h, l;
    split8v(v, h, l);
    *(uint4*)&hi[i] = h;
    *(uint4*)&lo[i] = l;
}

__global__ __launch_bounds__(256) void presplit_x(const float* __restrict__ s)
{ presplit_body(s, g_xhi, g_xlo); }

__global__ __launch_bounds__(256) void presplit_w1(const float* __restrict__ s)
{ presplit_body(s, g_w1hi, g_w1lo); }

__global__ __launch_bounds__(256) void presplit_w2(const float* __restrict__ s)
{ presplit_body(s, g_w2hi, g_w2lo); }

// ===========================================================================
// Tensor-core GEMM mainloop v2: CTA 128(M) x 256(N), 256 thr (8 warps, 2m x 4n),
// warp tile 64x64 (4 mt x 8 nt), BK=32, cp.async double-buffered staging.
// Stage layout (per 48KB stage): Ahi[0,8K) Alo[8K,16K) Bhi[16K,32K) Blo[32K,48K).
// Fragment mappings identical to the R10/R16-verified code.
// ===========================================================================
#define STAGE_BYTES 49152
#define GEMM_SMEM_DYN (2 * STAGE_BYTES)     // 96 KB

__device__ __forceinline__ void stage_chunk(
    uint32_t sbase,
    const __nv_bfloat16* __restrict__ Ahi, const __nv_bfloat16* __restrict__ Alo,
    const __nv_bfloat16* __restrict__ Bhi, const __nv_bfloat16* __restrict__ Blo,
    int m0, int n0, int K, int k0, int t)
{
    const int sr = t >> 1;                 // 0..127
    const int sh = t & 1;                  // k-half (16 elements)
    const uint32_t so0 = tile_off(sr, sh * 2);
    const uint32_t so1 = tile_off(sr, sh * 2 + 1);
    const uint32_t so2 = tile_off(sr + 128, sh * 2);
    const uint32_t so3 = tile_off(sr + 128, sh * 2 + 1);

    const size_t ab  = (size_t)(m0 + sr) * K + k0 + sh * 16;
    const size_t bb0 = (size_t)(n0 + sr) * K + k0 + sh * 16;
    const size_t bb1 = (size_t)(n0 + sr + 128) * K + k0 + sh * 16;

    cp16(sbase +          so0, Ahi + ab);      cp16(sbase +          so1, Ahi + ab + 8);
    cp16(sbase +  8192 +  so0, Alo + ab);      cp16(sbase +  8192 +  so1, Alo + ab + 8);
    cp16(sbase + 16384 +  so0, Bhi + bb0);     cp16(sbase + 16384 +  so1, Bhi + bb0 + 8);
    cp16(sbase + 16384 +  so2, Bhi + bb1);     cp16(sbase + 16384 +  so3, Bhi + bb1 + 8);
    cp16(sbase + 32768 +  so0, Blo + bb0);     cp16(sbase + 32768 +  so1, Blo + bb0 + 8);
    cp16(sbase + 32768 +  so2, Blo + bb1);     cp16(sbase + 32768 +  so3, Blo + bb1 + 8);
    cp_commit();
}

__device__ __forceinline__ void gemm_mainloop(
    const __nv_bfloat16* __restrict__ Ahi, const __nv_bfloat16* __restrict__ Alo,
    const __nv_bfloat16* __restrict__ Bhi, const __nv_bfloat16* __restrict__ Blo,
    int m0, int n0, int K, float d[4][8][4])
{
    extern __shared__ uint8_t smem[];
    const uint32_t sb = smem_u32(smem);

    const int t    = threadIdx.x;
    const int lane = t & 31;
    const int wid  = t >> 5;
    const int wm   = wid & 1;
    const int wn   = wid >> 1;              // 0..3 -> 64-col quarter

    const int arow = wm * 64 + (lane & 15);
    const int acol_lane = lane >> 4;
    const int brow = wn * 64 + (lane & 7);
    const int bcol_lane = (lane >> 3) & 1;

    #pragma unroll
    for (int mt = 0; mt < 4; mt++)
        #pragma unroll
        for (int nt = 0; nt < 8; nt++)
            #pragma unroll
            for (int e = 0; e < 4; e++) d[mt][nt][e] = 0.f;

    const int nchunk = K >> 5;
    stage_chunk(sb, Ahi, Alo, Bhi, Blo, m0, n0, K, 0, t);

    for (int c = 0; c < nchunk; c++) {
        const uint32_t buf = sb + (uint32_t)(c & 1) * STAGE_BYTES;
        if (c + 1 < nchunk) {
            stage_chunk(sb + (uint32_t)((c + 1) & 1) * STAGE_BYTES,
                        Ahi, Alo, Bhi, Blo, m0, n0, K, (c + 1) * 32, t);
            CP_WAIT(1);
        } else {
            CP_WAIT(0);
        }
        __syncthreads();

        #pragma unroll
        for (int ks = 0; ks < 2; ks++) {
            uint32_t a_hi[4][4], a_lo[4][4], b_hi[8][2], b_lo[8][2];
            #pragma unroll
            for (int mt = 0; mt < 4; mt++) {
                const uint32_t off = tile_off(arow + mt * 16, ks * 2 + acol_lane);
                ldmatrix_x4(a_hi[mt][0], a_hi[mt][1], a_hi[mt][2], a_hi[mt][3], buf + off);
                ldmatrix_x4(a_lo[mt][0], a_lo[mt][1], a_lo[mt][2], a_lo[mt][3], buf + 8192 + off);
            }
            #pragma unroll
            for (int nt = 0; nt < 8; nt++) {
                const uint32_t off = tile_off(brow + nt * 8, ks * 2 + bcol_lane);
                ldmatrix_x2(b_hi[nt][0], b_hi[nt][1], buf + 16384 + off);
                ldmatrix_x2(b_lo[nt][0], b_lo[nt][1], buf + 32768 + off);
            }
            #pragma unroll
            for (int mt = 0; mt < 4; mt++)
                #pragma unroll
                for (int nt = 0; nt < 8; nt++) {
                    mma_bf16(d[mt][nt], a_hi[mt], b_hi[nt]);
                    mma_bf16(d[mt][nt], a_hi[mt], b_lo[nt]);
                    mma_bf16(d[mt][nt], a_lo[mt], b_hi[nt]);
                }
        }
        __syncthreads();
    }
}

// GEMM1: qkv projection; fused epilogue scatters bf16 hi/lo q/k/v per head.
__global__ __launch_bounds__(256) void gemm1_tc()
{
    float d[4][8][4];
    const int m0 = blockIdx.y * 128;
    const int n0 = blockIdx.x * 256;
    gemm_mainloop(g_xhi, g_xlo, g_w1hi, g_w1lo, m0, n0, DMODEL, d);

    const int lane = threadIdx.x & 31;
    const int wid  = threadIdx.x >> 5;
    const int wm   = wid & 1;
    const int wn   = wid >> 1;
    const int er   = lane >> 2;
    const int ec   = (lane & 3) * 2;

    #pragma unroll
    for (int nt = 0; nt < 8; nt++) {
        const int col  = n0 + wn * 64 + nt * 8 + ec;    // 0..3071
        const int part = col >> 10;                      // 0=q 1=k 2=v
        const int h    = (col & 1023) >> 6;
        const int dd   = col & 63;
        __nv_bfloat16 *ph, *pl;
        float scale;
        if (part == 0)      { ph = g_qhi; pl = g_qlo; scale = 0.125f; }
        else if (part == 1) { ph = g_khi; pl = g_klo; scale = 1.0f; }
        else                { ph = g_vhi; pl = g_vlo; scale = 1.0f; }

        #pragma unroll
        for (int mt = 0; mt < 4; mt++) {
            #pragma unroll
            for (int hf = 0; hf < 2; hf++) {
                const int row = m0 + wm * 64 + mt * 16 + er + hf * 8;
                const int b   = row >> 11;               // row / SEQ
                const int s   = row & 2047;
                const size_t off = ((size_t)((b * 16 + h) * SEQ + s)) * HD + dd;
                uint32_t uh, ul;
                split2(d[mt][nt][hf*2 + 0] * scale, d[mt][nt][hf*2 + 1] * scale, uh, ul);
                *(uint32_t*)&ph[off] = uh;
                *(uint32_t*)&pl[off] = ul;
            }
        }
    }
}

// GEMM2: output projection + bias, fp32 out.
__global__ __launch_bounds__(256) void gemm2_tc(const float* __restrict__ bias,
                                                float* __restrict__ out)
{
    float d[4][8][4];
    const int m0 = blockIdx.y * 128;
    const int n0 = blockIdx.x * 256;
    gemm_mainloop(g_ahi, g_alo, g_w2hi, g_w2lo, m0, n0, DMODEL, d);

    const int lane = threadIdx.x & 31;
    const int wid  = threadIdx.x >> 5;
    const int wm   = wid & 1;
    const int wn   = wid >> 1;
    const int er   = lane >> 2;
    const int ec   = (lane & 3) * 2;

    #pragma unroll
    for (int nt = 0; nt < 8; nt++) {
        const int col = n0 + wn * 64 + nt * 8 + ec;
        const float bx = bias[col], by = bias[col + 1];
        #pragma unroll
        for (int mt = 0; mt < 4; mt++) {
            const int row = m0 + wm * 64 + mt * 16 + er;
            *(float2*)&out[(size_t)row * DMODEL + col] =
                make_float2(d[mt][nt][0] + bx, d[mt][nt][1] + by);
            *(float2*)&out[(size_t)(row + 8) * DMODEL + col] =
                make_float2(d[mt][nt][2] + bx, d[mt][nt][3] + by);
        }
    }
}

// ---------------------------------------------------------------------------
// Flash attention on tensor cores (verified R12/R16 — unchanged)
// Block 256 thr = 8 warps; q-tile 128; k-tiles of 64. grid (16, 64)
// ---------------------------------------------------------------------------
__global__ __launch_bounds__(256) void attn_mma()
{
    __shared__ __align__(128) uint8_t sbuf[32768];

    const int t    = threadIdx.x;
    const int lane = t & 31;
    const int wq   = t >> 5;
    const int bh   = blockIdx.y;
    const int b    = bh >> 4, h = bh & 15;
    const int q0   = blockIdx.x * 128;

    const uint32_t sB   = smem_u32(sbuf);
    const uint32_t sKhi = sB, sKlo = sB + 8192, sVhi = sB + 16384, sVlo = sB + 24576;
    const uint32_t sQhi = sB, sQlo = sB + 16384;

    const size_t headbase = (size_t)bh * SEQ * HD;

    #pragma unroll
    for (int u = 0; u < 4; u++) {
        const int i   = t * 4 + u;
        const int row = i >> 3;
        const int ch  = i & 7;
        const uint32_t so = swz128(row, ch);
        const size_t g = (headbase + (size_t)(q0 + row) * HD + ch * 8) / 8;
        *(uint4*)(sbuf + (sQhi - sB) + so) = ((const uint4*)g_qhi)[g];
        *(uint4*)(sbuf + (sQlo - sB) + so) = ((const uint4*)g_qlo)[g];
    }
    __syncthreads();

    uint32_t qhi[4][4], qlo[4][4];
    {
        const int arow = wq * 16 + (lane & 15);
        const int acl  = lane >> 4;
        #pragma unroll
        for (int ks = 0; ks < 4; ks++) {
            const uint32_t off = swz128(arow, ks * 2 + acl);
            ldmatrix_x4(qhi[ks][0], qhi[ks][1], qhi[ks][2], qhi[ks][3], sQhi + off);
            ldmatrix_x4(qlo[ks][0], qlo[ks][1], qlo[ks][2], qlo[ks][3], sQlo + off);
        }
    }
    __syncthreads();

    const int er  = lane >> 2;
    const int ec  = (lane & 3) * 2;
    const int kbr = lane & 7;
    const int kbc = (lane >> 3) & 1;
    const int vbr = lane & 15;

    const int si0 = t * 2, si1 = t * 2 + 1;
    const uint32_t kso0 = swz128(si0 >> 3, si0 & 7);
    const uint32_t kso1 = swz128(si1 >> 3, si1 & 7);

    float m0 = -INFINITY, m1 = -INFINITY, l0 = 0.f, l1 = 0.f;
    float o[8][4];
    #pragma unroll
    for (int dt = 0; dt < 8; dt++)
        #pragma unroll
        for (int e = 0; e < 4; e++) o[dt][e] = 0.f;

    uint4 pf[8];
    {
        const size_t g0 = (headbase + (size_t)(si0 >> 3) * HD + (si0 & 7) * 8) / 8;
        const size_t g1 = (headbase + (size_t)(si1 >> 3) * HD + (si1 & 7) * 8) / 8;
        pf[0] = ((const uint4*)g_khi)[g0]; pf[1] = ((const uint4*)g_khi)[g1];
        pf[2] = ((const uint4*)g_klo)[g0]; pf[3] = ((const uint4*)g_klo)[g1];
        pf[4] = ((const uint4*)g_vhi)[g0]; pf[5] = ((const uint4*)g_vhi)[g1];
        pf[6] = ((const uint4*)g_vlo)[g0]; pf[7] = ((const uint4*)g_vlo)[g1];
    }

    for (int kt = 0; kt < SEQ / 64; kt++) {
        *(uint4*)(sbuf + 0     + kso0) = pf[0]; *(uint4*)(sbuf + 0     + kso1) = pf[1];
        *(uint4*)(sbuf + 8192  + kso0) = pf[2]; *(uint4*)(sbuf + 8192  + kso1) = pf[3];
        *(uint4*)(sbuf + 16384 + kso0) = pf[4]; *(uint4*)(sbuf + 16384 + kso1) = pf[5];
        *(uint4*)(sbuf + 24576 + kso0) = pf[6]; *(uint4*)(sbuf + 24576 + kso1) = pf[7];
        __syncthreads();

        if (kt + 1 < SEQ / 64) {
            const size_t kb = headbase + (size_t)(kt + 1) * 64 * HD;
            const size_t g0 = (kb + (size_t)(si0 >> 3) * HD + (si0 & 7) * 8) / 8;
            const size_t g1 = (kb + (size_t)(si1 >> 3) * HD + (si1 & 7) * 8) / 8;
            pf[0] = ((const uint4*)g_khi)[g0]; pf[1] = ((const uint4*)g_khi)[g1];
            pf[2] = ((const uint4*)g_klo)[g0]; pf[3] = ((const uint4*)g_klo)[g1];
            pf[4] = ((const uint4*)g_vhi)[g0]; pf[5] = ((const uint4*)g_vhi)[g1];
            pf[6] = ((const uint4*)g_vlo)[g0]; pf[7] = ((const uint4*)g_vlo)[g1];
        }

        float s[8][4];
        #pragma unroll
        for (int nt = 0; nt < 8; nt++)
            #pragma unroll
            for (int e = 0; e < 4; e++) s[nt][e] = 0.f;

        #pragma unroll
        for (int ks = 0; ks < 4; ks++) {
            #pragma unroll
            for (int nt = 0; nt < 8; nt++) {
                uint32_t bhh[2], bll[2];
                const uint32_t off = swz128(nt * 8 + kbr, ks * 2 + kbc);
                ldmatrix_x2(bhh[0], bhh[1], sKhi + off);
                ldmatrix_x2(bll[0], bll[1], sKlo + off);
                mma_bf16(s[nt], qhi[ks], bhh);
                mma_bf16(s[nt], qhi[ks], bll);
                mma_bf16(s[nt], qlo[ks], bhh);
            }
        }

        float mx0 = s[0][0], mx1 = s[0][2];
        #pragma unroll
        for (int nt = 0; nt < 8; nt++) {
            mx0 = fmaxf(mx0, fmaxf(s[nt][0], s[nt][1]));
            mx1 = fmaxf(mx1, fmaxf(s[nt][2], s[nt][3]));
        }
        mx0 = fmaxf(mx0, __shfl_xor_sync(0xffffffffu, mx0, 1));
        mx0 = fmaxf(mx0, __shfl_xor_sync(0xffffffffu, mx0, 2));
        mx1 = fmaxf(mx1, __shfl_xor_sync(0xffffffffu, mx1, 1));
        mx1 = fmaxf(mx1, __shfl_xor_sync(0xffffffffu, mx1, 2));

        const float mn0 = fmaxf(m0, mx0);
        const float mn1 = fmaxf(m1, mx1);
        const float al0 = __expf(m0 - mn0);
        const float al1 = __expf(m1 - mn1);
        m0 = mn0; m1 = mn1;

        float rs0 = 0.f, rs1 = 0.f;
        #pragma unroll
        for (int nt = 0; nt < 8; nt++) {
            s[nt][0] = __expf(s[nt][0] - mn0);
            s[nt][1] = __expf(s[nt][1] - mn0);
            s[nt][2] = __expf(s[nt][2] - mn1);
            s[nt][3] = __expf(s[nt][3] - mn1);
            rs0 += s[nt][0] + s[nt][1];
            rs1 += s[nt][2] + s[nt][3];
        }
        rs0 += __shfl_xor_sync(0xffffffffu, rs0, 1);
        rs0 += __shfl_xor_sync(0xffffffffu, rs0, 2);
        rs1 += __shfl_xor_sync(0xffffffffu, rs1, 1);
        rs1 += __shfl_xor_sync(0xffffffffu, rs1, 2);
        l0 = l0 * al0 + rs0;
        l1 = l1 * al1 + rs1;

        #pragma unroll
        for (int dt = 0; dt < 8; dt++) {
            o[dt][0] *= al0; o[dt][1] *= al0;
            o[dt][2] *= al1; o[dt][3] *= al1;
        }

        uint32_t pa_hi[4][4], pa_lo[4][4];
        #pragma unroll
        for (int kk = 0; kk < 4; kk++) {
            #pragma unroll
            for (int half = 0; half < 2; half++) {
                const float* sv = s[2*kk + half];
                float rh[4], rl[4];
                #pragma unroll
                for (int e = 0; e < 4; e++) {
                    __nv_bfloat16 hh = __float2bfloat16_rn(sv[e]);
                    rh[e] = __bfloat162float(hh);
                    rl[e] = sv[e] - rh[e];
                }
                pa_hi[kk][half*2 + 0] = pack_bf16(rh[0], rh[1]);
                pa_hi[kk][half*2 + 1] = pack_bf16(rh[2], rh[3]);
                pa_lo[kk][half*2 + 0] = pack_bf16(rl[0], rl[1]);
                pa_lo[kk][half*2 + 1] = pack_bf16(rl[2], rl[3]);
            }
        }

        #pragma unroll
        for (int kk = 0; kk < 4; kk++) {
            #pragma unroll
            for (int dt = 0; dt < 8; dt++) {
                uint32_t bvh[2], bvl[2];
                const uint32_t off = swz128(kk * 16 + vbr, dt);
                ldmatrix_x2t(bvh[0], bvh[1], sVhi + off);
                ldmatrix_x2t(bvl[0], bvl[1], sVlo + off);
                mma_bf16(o[dt], pa_hi[kk], bvh);
                mma_bf16(o[dt], pa_hi[kk], bvl);
                mma_bf16(o[dt], pa_lo[kk], bvh);
            }
        }
        __syncthreads();
    }

    const float inv0 = 1.f / l0;
    const float inv1 = 1.f / l1;
    const int row0 = b * SEQ + q0 + wq * 16 + er;
    #pragma unroll
    for (int dt = 0; dt < 8; dt++) {
        const int col = h * HD + dt * 8 + ec;
        uint32_t uh, ul;
        split2(o[dt][0] * inv0, o[dt][1] * inv0, uh, ul);
        *(uint32_t*)&g_ahi[(size_t)row0 * DMODEL + col] = uh;
        *(uint32_t*)&g_alo[(size_t)row0 * DMODEL + col] = ul;
        split2(o[dt][2] * inv1, o[dt][3] * inv1, uh, ul);
        *(uint32_t*)&g_ahi[(size_t)(row0 + 8) * DMODEL + col] = uh;
        *(uint32_t*)&g_alo[(size_t)(row0 + 8) * DMODEL + col] = ul;
    }
}

// ---------------------------------------------------------------------------
extern "C" void kernel_launch(void* const* d_in, const int* in_sizes, int n_in,
                              void* d_out, int out_size)
{
    const float* x     = (const float*)d_in[0];   // [4,2048,1024]
    const float* w_qkv = (const float*)d_in[1];   // [3072,1024]
    const float* w_out = (const float*)d_in[2];   // [1024,1024]
    const float* b_out = (const float*)d_in[3];   // [1024]
    float* out = (float*)d_out;                   // [4,2048,1024]

    static bool attr_done = false;
    if (!attr_done) {
        cudaFuncSetAttribute(gemm1_tc, cudaFuncAttributeMaxDynamicSharedMemorySize, GEMM_SMEM_DYN);
        cudaFuncSetAttribute(gemm2_tc, cudaFuncAttributeMaxDynamicSharedMemorySize, GEMM_SMEM_DYN);
        attr_done = true;
    }

    // 0) Pre-split inputs to bf16 hi/lo (globals bound in device code!)
    presplit_x <<<(ROWS * DMODEL) / (256 * 8), 256>>>(x);
    presplit_w1<<<(TD * DMODEL) / (256 * 8), 256>>>(w_qkv);
    presplit_w2<<<(DMODEL * DMODEL) / (256 * 8), 256>>>(w_out);

    // 1) QKV projection, fused per-head split-scatter (Q scaled)
    gemm1_tc<<<dim3(TD / 256, ROWS / 128), 256, GEMM_SMEM_DYN>>>();

    // 2) Flash attention on tensor cores -> g_ahi/g_alo
    attn_mma<<<dim3(SEQ / 128, NBH), 256>>>();

    // 3) Output projection + bias -> d_out
    gemm2_tc<<<dim3(DMODEL / 256, ROWS / 128), 256, GEMM_SMEM_DYN>>>(b_out, out);
}